// round 15
// baseline (speedup 1.0000x reference)
#include <cuda_runtime.h>
#include <cuda_fp16.h>
#include <math.h>
#include <stdint.h>

#define SEQ  4096
#define HDIM 768
#define NHEAD 12
#define HD   64

#define NKT16 (HDIM / 16)                 // 48 k16-tiles
#define XP_WORDS (32 * NKT16 * 1024)
#define WP_WORDS (6  * NKT16 * 1024)
#define NCTA ((SEQ / 128) * NHEAD)        // 384 (mb,h) units

// Scratch (fp16x2 packed in uint32)
__device__ uint32_t g_qp[32 * NHEAD * 4096];     // Q flash-A frags per (mb128,h)
__device__ uint32_t g_k2[NHEAD * 64 * 2048];     // K flash-B frags per (h,T)
__device__ uint32_t g_v2[NHEAD * 64 * 2048];     // V flash-B frags per (h,T)
__device__ uint32_t g_xp[XP_WORDS];              // x, GEMM-A layout
__device__ uint32_t g_xkvp[XP_WORDS];            // gathered x, GEMM-A layout
__device__ uint32_t g_ctxp[XP_WORDS];            // ctx, GEMM-A layout
__device__ uint32_t g_wp[4][WP_WORDS];           // W*, GEMM-B layout (paired nt)
__device__ float    g_pacc[2 * NCTA * 4 * 2 * 8 * 128];  // split-kv partial acc
__device__ float    g_pl[2 * NCTA * 4 * 2 * 64];         // split-kv partial l
__device__ int      g_kidx[SEQ];
__device__ int      g_cnt;

#define ONES_H2 0x3C003C00u   // half2(1.0, 1.0)

__device__ __forceinline__ uint32_t pack2(float lo, float hi) {
    __half2 h = __floats2half2_rn(lo, hi);
    return *(uint32_t*)&h;
}

__device__ __forceinline__ uint32_t h2ex2(uint32_t x) {
    uint32_t y;
    asm("ex2.approx.f16x2 %0, %1;" : "=r"(y) : "r"(x));
    return y;
}

__device__ __forceinline__ void mma_f16(float c[4],
                                        uint32_t a0, uint32_t a1, uint32_t a2, uint32_t a3,
                                        uint32_t b0, uint32_t b1) {
    asm volatile("mma.sync.aligned.m16n8k16.row.col.f32.f16.f16.f32 "
                 "{%0,%1,%2,%3}, {%4,%5,%6,%7}, {%8,%9}, {%0,%1,%2,%3};"
                 : "+f"(c[0]), "+f"(c[1]), "+f"(c[2]), "+f"(c[3])
                 : "r"(a0), "r"(a1), "r"(a2), "r"(a3), "r"(b0), "r"(b1));
}

__device__ __forceinline__ void cp16(uint32_t smem_addr, const void* gptr) {
    asm volatile("cp.async.cg.shared.global [%0], [%1], 16;"
                 :: "r"(smem_addr), "l"(gptr));
}
#define CP_COMMIT() asm volatile("cp.async.commit_group;")
#define CP_WAIT1()  asm volatile("cp.async.wait_group 1;")
#define CP_WAIT2()  asm volatile("cp.async.wait_group 2;")

// ---------------------------------------------------------------------------
// Compaction (unchanged)
// ---------------------------------------------------------------------------
__global__ void compact_kernel(const int* __restrict__ mask) {
    __shared__ int wsum[32];
    int tid = threadIdx.x, lane = tid & 31, wid = tid >> 5;
    int f[4];
    int c = 0;
    #pragma unroll
    for (int r = 0; r < 4; r++) {
        f[r] = (mask[tid * 4 + r] == 0) ? 1 : 0;
        c += f[r];
    }
    int inc = c;
    #pragma unroll
    for (int o = 1; o < 32; o <<= 1) {
        int n = __shfl_up_sync(0xffffffffu, inc, o);
        if (lane >= o) inc += n;
    }
    if (lane == 31) wsum[wid] = inc;
    __syncthreads();
    if (wid == 0) {
        int v = wsum[lane];
        int s = v;
        #pragma unroll
        for (int o = 1; o < 32; o <<= 1) {
            int n = __shfl_up_sync(0xffffffffu, s, o);
            if (lane >= o) s += n;
        }
        wsum[lane] = s - v;
        if (lane == 31) g_cnt = s;
    }
    __syncthreads();
    int base = wsum[wid] + inc - c;
    #pragma unroll
    for (int r = 0; r < 4; r++) {
        if (f[r]) g_kidx[base++] = tid * 4 + r;
    }
}

// ---------------------------------------------------------------------------
// Permute x -> g_xp (z=0) and gathered x -> g_xkvp (z=1). grid (48, 32, 2).
// ---------------------------------------------------------------------------
__global__ __launch_bounds__(256)
void permute_x_kernel(const float* __restrict__ x) {
    int kt = blockIdx.x, mb = blockIdx.y, z = blockIdx.z;
    int cnt = g_cnt;
    if (z == 1 && mb * 128 >= cnt) return;
    int st = threadIdx.x >> 5, l = threadIdx.x & 31;
    uint32_t w[4];
    #pragma unroll
    for (int wi = 0; wi < 4; wi++) {
        int m = mb * 128 + st * 16 + (wi & 1) * 8 + (l >> 2);
        int k = kt * 16 + (wi >> 1) * 8 + 2 * (l & 3);
        float v0 = 0.f, v1 = 0.f;
        if (z == 0) {
            const float* p = x + (size_t)m * HDIM + k;
            v0 = p[0]; v1 = p[1];
        } else if (m < cnt) {
            const float* p = x + (size_t)g_kidx[m] * HDIM + k;
            v0 = p[0]; v1 = p[1];
        }
        w[wi] = pack2(v0, v1);
    }
    uint32_t* dst = (z == 0) ? g_xp : g_xkvp;
    *(uint4*)&dst[((size_t)(mb * NKT16 + kt) * 8 + st) * 128 + l * 4] = *(uint4*)w;
}

// ---------------------------------------------------------------------------
// Permute W -> g_wp[z], paired n-subtile layout. grid (48, 6, 4).
// ---------------------------------------------------------------------------
__global__ __launch_bounds__(256)
void permute_w_kernel(const float* __restrict__ Wq, const float* __restrict__ Wk,
                      const float* __restrict__ Wv, const float* __restrict__ Wo) {
    int kt = blockIdx.x, nb = blockIdx.y, z = blockIdx.z;
    const float* W = (z == 0) ? Wq : (z == 1) ? Wk : (z == 2) ? Wv : Wo;
    int p = threadIdx.x >> 5, l = threadIdx.x & 31;
    uint32_t w[4];
    #pragma unroll
    for (int wi = 0; wi < 4; wi++) {
        int nt = p * 2 + (wi >> 1);
        int ki = wi & 1;
        int n = nb * 128 + nt * 8 + (l >> 2);
        int k = kt * 16 + ki * 8 + 2 * (l & 3);
        const float* ptr = W + (size_t)n * HDIM + k;
        w[wi] = pack2(ptr[0], ptr[1]);
    }
    *(uint4*)&g_wp[z][((size_t)(nb * NKT16 + kt)) * 1024 + ((size_t)p * 32 + l) * 4] =
        *(uint4*)w;
}

// ---------------------------------------------------------------------------
// fp16 GEMM mainloop (unchanged from R14)
// ---------------------------------------------------------------------------
__device__ __forceinline__ void gemm_main(uint32_t* sg,
                                          const uint32_t* __restrict__ Ap,
                                          const uint32_t* __restrict__ Bp,
                                          float acc[2][8][4]) {
    int tid = threadIdx.x;
    int lane = tid & 31, warp = tid >> 5;
    int warp_m = warp & 3, warp_n = warp >> 2;
    uint32_t smem_base = (uint32_t)__cvta_generic_to_shared(sg);

    const uint4* Asrc = (const uint4*)Ap;
    const uint4* Bsrc = (const uint4*)Bp;

    auto pf = [&](int s, int st) {
        uint32_t da = smem_base + (uint32_t)st * 16384u;
        const uint4* a = Asrc + (size_t)s * 512;
        const uint4* b = Bsrc + (size_t)s * 512;
        #pragma unroll
        for (int i = 0; i < 2; i++) {
            int o = i * 256 + tid;
            cp16(da + (uint32_t)o * 16u, a + o);
            cp16(da + 8192u + (uint32_t)o * 16u, b + o);
        }
    };

    pf(0, 0); CP_COMMIT();
    pf(1, 1); CP_COMMIT();
    pf(2, 2); CP_COMMIT();

    const int NST = HDIM / 32;   // 24 stages
    for (int s = 0; s < NST; s++) {
        CP_WAIT2();
        __syncthreads();
        if (s + 3 < NST) pf(s + 3, (s + 3) & 3);
        CP_COMMIT();
        uint32_t* A = sg + (s & 3) * 4096;
        uint32_t* B = A + 2048;
        #pragma unroll
        for (int kt = 0; kt < 2; kt++) {
            const uint32_t* Ak = A + kt * 1024;
            const uint32_t* Bk = B + kt * 1024;
            uint4 a0 = *(const uint4*)&Ak[((warp_m * 2 + 0) * 32 + lane) * 4];
            uint4 a1 = *(const uint4*)&Ak[((warp_m * 2 + 1) * 32 + lane) * 4];
            #pragma unroll
            for (int ntp = 0; ntp < 4; ntp++) {
                uint4 b = *(const uint4*)&Bk[((warp_n * 4 + ntp) * 32 + lane) * 4];
                mma_f16(acc[0][2 * ntp],     a0.x, a0.y, a0.z, a0.w, b.x, b.y);
                mma_f16(acc[0][2 * ntp + 1], a0.x, a0.y, a0.z, a0.w, b.z, b.w);
                mma_f16(acc[1][2 * ntp],     a1.x, a1.y, a1.z, a1.w, b.x, b.y);
                mma_f16(acc[1][2 * ntp + 1], a1.x, a1.y, a1.z, a1.w, b.z, b.w);
            }
        }
    }
}

#define GEMM_SMEM (4 * 4096 * 4)

// ---------------------------------------------------------------------------
// Projection kernel (unchanged from R14)
// ---------------------------------------------------------------------------
__global__ __launch_bounds__(256)
void proj_kernel(const float* __restrict__ bq, const float* __restrict__ bk,
                 const float* __restrict__ bv) {
    extern __shared__ uint32_t sg[];
    int z = blockIdx.z;
    int mb = blockIdx.y;
    int cnt = g_cnt;
    if (z > 0 && mb * 128 >= cnt) return;

    const uint32_t* Ap = ((z == 0) ? g_xp : g_xkvp) + (size_t)mb * NKT16 * 1024;
    const uint32_t* Bp = g_wp[z] + (size_t)blockIdx.x * NKT16 * 1024;
    const float* bias = (z == 0) ? bq : (z == 1) ? bk : bv;

    float acc[2][8][4] = {};
    gemm_main(sg, Ap, Bp, acc);

    int tid = threadIdx.x;
    int lane = tid & 31, warp = tid >> 5;
    int g = lane >> 2, tg = lane & 3;
    int warp_m = warp & 3, warp_n = warp >> 2;
    int h = blockIdx.x * 2 + warp_n;

    if (z == 0) {
        uint32_t* dst = g_qp + (size_t)(mb * NHEAD + h) * 4096;
        #pragma unroll
        for (int i = 0; i < 2; i++) {
            int mt = warp_m * 2 + i;
            #pragma unroll
            for (int nt = 0; nt < 8; nt++) {
                int dd0 = nt * 8 + 2 * tg;
                float bx = bias[h * 64 + dd0], by = bias[h * 64 + dd0 + 1];
                int kt = nt >> 1;
                uint32_t o = (uint32_t)((kt * 8 + mt) * 32 + lane) * 4 + (nt & 1) * 2;
                uint2 v;
                v.x = pack2(acc[i][nt][0] + bx, acc[i][nt][1] + by);
                v.y = pack2(acc[i][nt][2] + bx, acc[i][nt][3] + by);
                *(uint2*)&dst[o] = v;
            }
        }
    } else if (z == 1) {
        #pragma unroll
        for (int i = 0; i < 2; i++) {
            int j0 = mb * 128 + warp_m * 32 + i * 16 + g;
            #pragma unroll
            for (int nt = 0; nt < 8; nt++) {
                int dd0 = nt * 8 + 2 * tg;
                float bx = bias[h * 64 + dd0], by = bias[h * 64 + dd0 + 1];
                int ktp = nt >> 2;
                int wi = ((nt >> 1) & 1) * 2 + (nt & 1);
                #pragma unroll
                for (int r = 0; r < 2; r++) {
                    int j = j0 + r * 8;
                    int T = j >> 6, jj = j & 63;
                    uint32_t base = (uint32_t)(h * 64 + T) * 2048;
                    uint32_t o = base + (uint32_t)(((jj >> 3) * 2 + ktp) * 32
                                 + (jj & 7) * 4 + tg) * 4 + wi;
                    g_k2[o] = pack2(acc[i][nt][r * 2 + 0] + bx,
                                    acc[i][nt][r * 2 + 1] + by);
                }
            }
        }
    } else {
        __half* dst = (__half*)g_v2;
        #pragma unroll
        for (int i = 0; i < 2; i++) {
            int j0 = mb * 128 + warp_m * 32 + i * 16 + g;
            #pragma unroll
            for (int nt = 0; nt < 8; nt++) {
                int dd0 = nt * 8 + 2 * tg;
                float bx = bias[h * 64 + dd0], by = bias[h * 64 + dd0 + 1];
                #pragma unroll
                for (int r = 0; r < 2; r++) {
                    int j = j0 + r * 8;
                    int T = j >> 6, jj = j & 63;
                    int wi = ((jj >> 4) & 1) * 2 + ((jj >> 3) & 1);
                    int ktp = jj >> 5;
                    int lq = (jj >> 1) & 3;
                    int e = jj & 1;
                    #pragma unroll
                    for (int c = 0; c < 2; c++) {
                        int dd = dd0 + c;
                        int l = (dd & 7) * 4 + lq;
                        size_t hidx = (((size_t)(h * 64 + T) * 2048
                                      + ((dd >> 3) * 2 + ktp) * 128 + (l * 4 + wi))) * 2 + e;
                        dst[hidx] = __float2half_rn(acc[i][nt][r * 2 + c] + (c ? by : bx));
                    }
                }
            }
        }
    }
}

__global__ __launch_bounds__(256)
void oproj_kernel(const float* __restrict__ bo, float* __restrict__ out) {
    extern __shared__ uint32_t sg[];
    int mb = blockIdx.y;
    float acc[2][8][4] = {};
    gemm_main(sg, g_ctxp + (size_t)mb * NKT16 * 1024,
              g_wp[3] + (size_t)blockIdx.x * NKT16 * 1024, acc);

    int tid = threadIdx.x;
    int lane = tid & 31, warp = tid >> 5;
    int g = lane >> 2, tg = lane & 3;
    int warp_m = warp & 3, warp_n = warp >> 2;
    int mbase = mb * 128, nbase = blockIdx.x * 128;
    #pragma unroll
    for (int i = 0; i < 2; i++) {
        int m0 = mbase + warp_m * 32 + i * 16 + g;
        #pragma unroll
        for (int nt = 0; nt < 8; nt++) {
            int n0 = nbase + warp_n * 64 + nt * 8 + 2 * tg;
            float bx = bo[n0], by = bo[n0 + 1];
            *(float2*)(out + (size_t)m0 * HDIM + n0) =
                make_float2(acc[i][nt][0] + bx, acc[i][nt][1] + by);
            *(float2*)(out + (size_t)(m0 + 8) * HDIM + n0) =
                make_float2(acc[i][nt][2] + bx, acc[i][nt][3] + by);
        }
    }
}

// ---------------------------------------------------------------------------
// Flash attention, SPLIT-KV: grid (32, 12, 2); z = kv half. Each CTA runs the
// R14 mainloop over its half of the kv tiles and writes fp32 partials
// (acc, l) — combinable by plain addition because C=0 softmax has no max
// state. Halves the work-unit size -> better wave packing (768 units / 296
// slots: makespan 1.5 T vs 2.0 T).
// ---------------------------------------------------------------------------
#define FLASH_SMEM (8192 * 4)
#define CEXP 0.18033688f   // 0.125 * log2(e)

__global__ __launch_bounds__(128)
void flash_kernel() {
    extern __shared__ uint32_t sm[];
    int tid = threadIdx.x;
    int lane = tid & 31, warp = tid >> 5;
    int tg = lane & 3;
    int h = blockIdx.y, mb = blockIdx.x, half = blockIdx.z;
    int cnt = g_cnt;
    uint32_t smem_base = (uint32_t)__cvta_generic_to_shared(sm);

    const uint4* Ksrc = (const uint4*)(g_k2 + (size_t)h * 64 * 2048);
    const uint4* Vsrc = (const uint4*)(g_v2 + (size_t)h * 64 * 2048);
    int ntile = (cnt + 63) >> 6;
    int htiles = (ntile + 1) >> 1;
    int t0 = half * htiles;
    int t1 = min(ntile, t0 + htiles);

    auto prefetch = [&](int t, int buf) {
        uint32_t dk = smem_base + (uint32_t)buf * 16384u;
        const uint4* sk = Ksrc + (size_t)t * 512;
        const uint4* sv = Vsrc + (size_t)t * 512;
        #pragma unroll
        for (int i = 0; i < 4; i++) {
            int o = i * 128 + tid;
            cp16(dk + (uint32_t)o * 16u, sk + o);
            cp16(dk + 8192u + (uint32_t)o * 16u, sv + o);
        }
    };

    if (t0 < t1) prefetch(t0, 0);
    CP_COMMIT();

    // Q fragments (overlap with first prefetch)
    const uint32_t* Qsrc = g_qp + (size_t)(mb * NHEAD + h) * 4096;
    uint4 q[4][2];
    #pragma unroll
    for (int kt = 0; kt < 4; kt++)
        #pragma unroll
        for (int mtl = 0; mtl < 2; mtl++)
            q[kt][mtl] = *(const uint4*)&Qsrc[((kt * 8 + warp * 2 + mtl) * 32 + lane) * 4];

    float lacc[2][4] = {};        // denominator via mma (cols duplicated)
    float acc[2][8][4] = {};

    for (int t = t0; t < t1; t++) {
        int lt = t - t0;
        int cur = lt & 1;
        int kvb = t * 64;
        __syncthreads();
        if (t + 1 < t1) prefetch(t + 1, cur ^ 1);
        CP_COMMIT();
        CP_WAIT1();
        __syncthreads();
        uint32_t* Kp = sm + cur * 4096;
        uint32_t* Vp = Kp + 2048;

        // S = Q K^T (warp: 32x64)
        float sc[2][8][4] = {};
        #pragma unroll
        for (int ktp = 0; ktp < 2; ktp++) {
            #pragma unroll
            for (int nt = 0; nt < 8; nt++) {
                uint4 kb = *(const uint4*)&Kp[((nt * 2 + ktp) * 32 + lane) * 4];
                #pragma unroll
                for (int mtl = 0; mtl < 2; mtl++) {
                    uint4 a = q[2 * ktp][mtl];
                    mma_f16(sc[mtl][nt], a.x, a.y, a.z, a.w, kb.x, kb.y);
                    uint4 a2 = q[2 * ktp + 1][mtl];
                    mma_f16(sc[mtl][nt], a2.x, a2.y, a2.z, a2.w, kb.z, kb.w);
                }
            }
        }

        bool tail = (kvb + 64 > cnt);
        uint32_t pA[4][2][4];
        #pragma unroll
        for (int mtl = 0; mtl < 2; mtl++) {
            if (tail) {
                #pragma unroll
                for (int nt = 0; nt < 8; nt++) {
                    int c0 = kvb + nt * 8 + 2 * tg;
                    if (c0     >= cnt) { sc[mtl][nt][0] = -1e30f; sc[mtl][nt][2] = -1e30f; }
                    if (c0 + 1 >= cnt) { sc[mtl][nt][1] = -1e30f; sc[mtl][nt][3] = -1e30f; }
                }
            }
            // scale, pack to half2, exp2 in f16x2 -> P fragments directly
            #pragma unroll
            for (int nt = 0; nt < 8; nt++) {
                #pragma unroll
                for (int e = 0; e < 4; e++)
                    sc[mtl][nt][e] *= CEXP;
            }
            #pragma unroll
            for (int kt = 0; kt < 4; kt++) {
                pA[kt][mtl][0] = h2ex2(pack2(sc[mtl][2 * kt][0],     sc[mtl][2 * kt][1]));
                pA[kt][mtl][1] = h2ex2(pack2(sc[mtl][2 * kt][2],     sc[mtl][2 * kt][3]));
                pA[kt][mtl][2] = h2ex2(pack2(sc[mtl][2 * kt + 1][0], sc[mtl][2 * kt + 1][1]));
                pA[kt][mtl][3] = h2ex2(pack2(sc[mtl][2 * kt + 1][2], sc[mtl][2 * kt + 1][3]));
            }
            // denominator: lacc += P @ ones
            #pragma unroll
            for (int kt = 0; kt < 4; kt++)
                mma_f16(lacc[mtl], pA[kt][mtl][0], pA[kt][mtl][1],
                        pA[kt][mtl][2], pA[kt][mtl][3], ONES_H2, ONES_H2);
        }

        // acc += P @ V
        #pragma unroll
        for (int ktp = 0; ktp < 2; ktp++) {
            #pragma unroll
            for (int nt = 0; nt < 8; nt++) {
                uint4 vb = *(const uint4*)&Vp[((nt * 2 + ktp) * 32 + lane) * 4];
                #pragma unroll
                for (int mtl = 0; mtl < 2; mtl++) {
                    uint32_t* a = pA[2 * ktp][mtl];
                    mma_f16(acc[mtl][nt], a[0], a[1], a[2], a[3], vb.x, vb.y);
                    uint32_t* a2 = pA[2 * ktp + 1][mtl];
                    mma_f16(acc[mtl][nt], a2[0], a2[1], a2[2], a2[3], vb.z, vb.w);
                }
            }
        }
    }

    // epilogue: write fp32 partials (acc, l) for this kv half
    int cta = mb * NHEAD + h;
    #pragma unroll
    for (int mtl = 0; mtl < 2; mtl++) {
        size_t p = (((size_t)half * NCTA + cta) * 4 + warp) * 2 + mtl;
        g_pl[p * 64 + lane * 2]     = lacc[mtl][0];
        g_pl[p * 64 + lane * 2 + 1] = lacc[mtl][2];
        #pragma unroll
        for (int nt = 0; nt < 8; nt++)
            *(float4*)&g_pacc[(p * 8 + nt) * 128 + lane * 4] = *(float4*)acc[mtl][nt];
    }
}

// ---------------------------------------------------------------------------
// Combine split-kv partials: sum acc and l across halves, normalize, write
// g_ctxp in GEMM-A fragment layout. grid (384), block 128.
// ---------------------------------------------------------------------------
__global__ __launch_bounds__(128)
void combine_kernel() {
    int cta = blockIdx.x;
    int tid = threadIdx.x;
    int lane = tid & 31, warp = tid >> 5;
    int mb = cta / NHEAD, h = cta - mb * NHEAD;
    #pragma unroll
    for (int mtl = 0; mtl < 2; mtl++) {
        size_t p0 = ((size_t)cta * 4 + warp) * 2 + mtl;
        size_t p1 = (((size_t)NCTA + cta) * 4 + warp) * 2 + mtl;
        float l0 = g_pl[p0 * 64 + lane * 2]     + g_pl[p1 * 64 + lane * 2];
        float l1 = g_pl[p0 * 64 + lane * 2 + 1] + g_pl[p1 * 64 + lane * 2 + 1];
        float i0 = 1.0f / l0, i1 = 1.0f / l1;
        int mt = warp * 2 + mtl;
        #pragma unroll
        for (int nt = 0; nt < 8; nt++) {
            float4 a = *(const float4*)&g_pacc[(p0 * 8 + nt) * 128 + lane * 4];
            float4 b = *(const float4*)&g_pacc[(p1 * 8 + nt) * 128 + lane * 4];
            int kt16 = h * 4 + (nt >> 1);
            uint32_t o = ((uint32_t)(mb * NKT16 + kt16) * 8 + mt) * 128
                       + lane * 4 + (nt & 1) * 2;
            uint2 v;
            v.x = pack2((a.x + b.x) * i0, (a.y + b.y) * i0);
            v.y = pack2((a.z + b.z) * i1, (a.w + b.w) * i1);
            *(uint2*)&g_ctxp[o] = v;
        }
    }
}

// ---------------------------------------------------------------------------
extern "C" void kernel_launch(void* const* d_in, const int* in_sizes, int n_in,
                              void* d_out, int out_size) {
    const float* x  = (const float*)d_in[0];
    const float* Wq = (const float*)d_in[1];
    const float* bq = (const float*)d_in[2];
    const float* Wk = (const float*)d_in[3];
    const float* bk = (const float*)d_in[4];
    const float* Wv = (const float*)d_in[5];
    const float* bv = (const float*)d_in[6];
    const float* Wo = (const float*)d_in[7];
    const float* bo = (const float*)d_in[8];
    const int*   mask = (const int*)d_in[9];
    float* out = (float*)d_out;

    cudaFuncSetAttribute(flash_kernel, cudaFuncAttributeMaxDynamicSharedMemorySize,
                         FLASH_SMEM);
    cudaFuncSetAttribute(proj_kernel, cudaFuncAttributeMaxDynamicSharedMemorySize,
                         GEMM_SMEM);
    cudaFuncSetAttribute(oproj_kernel, cudaFuncAttributeMaxDynamicSharedMemorySize,
                         GEMM_SMEM);

    compact_kernel<<<1, 1024>>>(mask);
    permute_x_kernel<<<dim3(NKT16, 32, 2), 256>>>(x);
    permute_w_kernel<<<dim3(NKT16, 6, 4), 256>>>(Wq, Wk, Wv, Wo);
    proj_kernel<<<dim3(6, 32, 3), 256, GEMM_SMEM>>>(bq, bk, bv);
    flash_kernel<<<dim3(SEQ / 128, NHEAD, 2), 128, FLASH_SMEM>>>();
    combine_kernel<<<NCTA, 128>>>();
    oproj_kernel<<<dim3(6, 32), 256, GEMM_SMEM>>>(bo, out);
}

// round 16
// speedup vs baseline: 1.0668x; 1.0668x over previous
#include <cuda_runtime.h>
#include <cuda_fp16.h>
#include <math.h>
#include <stdint.h>

#define SEQ  4096
#define HDIM 768
#define NHEAD 12
#define HD   64

#define NKT16 (HDIM / 16)                 // 48 k16-tiles
#define XP_WORDS (32 * NKT16 * 1024)
#define WP_WORDS (6  * NKT16 * 1024)

// Scratch (fp16x2 packed in uint32)
__device__ uint32_t g_qp[32 * NHEAD * 4096];     // Q flash-A frags (pre-scaled)
__device__ uint32_t g_k2[NHEAD * 64 * 2048];     // K flash-B frags per (h,T)
__device__ uint32_t g_v2[NHEAD * 64 * 2048];     // V flash-B frags per (h,T)
__device__ uint32_t g_xp[XP_WORDS];              // x, GEMM-A layout
__device__ uint32_t g_xkvp[XP_WORDS];            // gathered x, GEMM-A layout
__device__ uint32_t g_ctxp[XP_WORDS];            // ctx, GEMM-A layout
__device__ uint32_t g_wp[4][WP_WORDS];           // W*, GEMM-B layout (paired nt)
__device__ int      g_kidx[SEQ];
__device__ int      g_cnt;

#define ONES_H2 0x3C003C00u   // half2(1.0, 1.0)
#define CEXP 0.18033688f      // 0.125 * log2(e)

__device__ __forceinline__ uint32_t pack2(float lo, float hi) {
    __half2 h = __floats2half2_rn(lo, hi);
    return *(uint32_t*)&h;
}

__device__ __forceinline__ uint32_t h2ex2(uint32_t x) {
    uint32_t y;
    asm("ex2.approx.f16x2 %0, %1;" : "=r"(y) : "r"(x));
    return y;
}

__device__ __forceinline__ void mma_f16(float c[4],
                                        uint32_t a0, uint32_t a1, uint32_t a2, uint32_t a3,
                                        uint32_t b0, uint32_t b1) {
    asm volatile("mma.sync.aligned.m16n8k16.row.col.f32.f16.f16.f32 "
                 "{%0,%1,%2,%3}, {%4,%5,%6,%7}, {%8,%9}, {%0,%1,%2,%3};"
                 : "+f"(c[0]), "+f"(c[1]), "+f"(c[2]), "+f"(c[3])
                 : "r"(a0), "r"(a1), "r"(a2), "r"(a3), "r"(b0), "r"(b1));
}

__device__ __forceinline__ void cp16(uint32_t smem_addr, const void* gptr) {
    asm volatile("cp.async.cg.shared.global [%0], [%1], 16;"
                 :: "r"(smem_addr), "l"(gptr));
}
#define CP_COMMIT() asm volatile("cp.async.commit_group;")
#define CP_WAIT1()  asm volatile("cp.async.wait_group 1;")
#define CP_WAIT2()  asm volatile("cp.async.wait_group 2;")

// ---------------------------------------------------------------------------
// Compaction (unchanged)
// ---------------------------------------------------------------------------
__global__ void compact_kernel(const int* __restrict__ mask) {
    __shared__ int wsum[32];
    int tid = threadIdx.x, lane = tid & 31, wid = tid >> 5;
    int f[4];
    int c = 0;
    #pragma unroll
    for (int r = 0; r < 4; r++) {
        f[r] = (mask[tid * 4 + r] == 0) ? 1 : 0;
        c += f[r];
    }
    int inc = c;
    #pragma unroll
    for (int o = 1; o < 32; o <<= 1) {
        int n = __shfl_up_sync(0xffffffffu, inc, o);
        if (lane >= o) inc += n;
    }
    if (lane == 31) wsum[wid] = inc;
    __syncthreads();
    if (wid == 0) {
        int v = wsum[lane];
        int s = v;
        #pragma unroll
        for (int o = 1; o < 32; o <<= 1) {
            int n = __shfl_up_sync(0xffffffffu, s, o);
            if (lane >= o) s += n;
        }
        wsum[lane] = s - v;
        if (lane == 31) g_cnt = s;
    }
    __syncthreads();
    int base = wsum[wid] + inc - c;
    #pragma unroll
    for (int r = 0; r < 4; r++) {
        if (f[r]) g_kidx[base++] = tid * 4 + r;
    }
}

// ---------------------------------------------------------------------------
// Permute x -> g_xp (z=0) and gathered x -> g_xkvp (z=1). grid (48, 32, 2).
// ---------------------------------------------------------------------------
__global__ __launch_bounds__(256)
void permute_x_kernel(const float* __restrict__ x) {
    int kt = blockIdx.x, mb = blockIdx.y, z = blockIdx.z;
    int cnt = g_cnt;
    if (z == 1 && mb * 128 >= cnt) return;
    int st = threadIdx.x >> 5, l = threadIdx.x & 31;
    uint32_t w[4];
    #pragma unroll
    for (int wi = 0; wi < 4; wi++) {
        int m = mb * 128 + st * 16 + (wi & 1) * 8 + (l >> 2);
        int k = kt * 16 + (wi >> 1) * 8 + 2 * (l & 3);
        float v0 = 0.f, v1 = 0.f;
        if (z == 0) {
            const float* p = x + (size_t)m * HDIM + k;
            v0 = p[0]; v1 = p[1];
        } else if (m < cnt) {
            const float* p = x + (size_t)g_kidx[m] * HDIM + k;
            v0 = p[0]; v1 = p[1];
        }
        w[wi] = pack2(v0, v1);
    }
    uint32_t* dst = (z == 0) ? g_xp : g_xkvp;
    *(uint4*)&dst[((size_t)(mb * NKT16 + kt) * 8 + st) * 128 + l * 4] = *(uint4*)w;
}

// ---------------------------------------------------------------------------
// Permute W -> g_wp[z], paired n-subtile layout. grid (48, 6, 4).
// ---------------------------------------------------------------------------
__global__ __launch_bounds__(256)
void permute_w_kernel(const float* __restrict__ Wq, const float* __restrict__ Wk,
                      const float* __restrict__ Wv, const float* __restrict__ Wo) {
    int kt = blockIdx.x, nb = blockIdx.y, z = blockIdx.z;
    const float* W = (z == 0) ? Wq : (z == 1) ? Wk : (z == 2) ? Wv : Wo;
    int p = threadIdx.x >> 5, l = threadIdx.x & 31;
    uint32_t w[4];
    #pragma unroll
    for (int wi = 0; wi < 4; wi++) {
        int nt = p * 2 + (wi >> 1);
        int ki = wi & 1;
        int n = nb * 128 + nt * 8 + (l >> 2);
        int k = kt * 16 + ki * 8 + 2 * (l & 3);
        const float* ptr = W + (size_t)n * HDIM + k;
        w[wi] = pack2(ptr[0], ptr[1]);
    }
    *(uint4*)&g_wp[z][((size_t)(nb * NKT16 + kt)) * 1024 + ((size_t)p * 32 + l) * 4] =
        *(uint4*)w;
}

// ---------------------------------------------------------------------------
// fp16 GEMM mainloop (unchanged from R14)
// ---------------------------------------------------------------------------
__device__ __forceinline__ void gemm_main(uint32_t* sg,
                                          const uint32_t* __restrict__ Ap,
                                          const uint32_t* __restrict__ Bp,
                                          float acc[2][8][4]) {
    int tid = threadIdx.x;
    int lane = tid & 31, warp = tid >> 5;
    int warp_m = warp & 3, warp_n = warp >> 2;
    uint32_t smem_base = (uint32_t)__cvta_generic_to_shared(sg);

    const uint4* Asrc = (const uint4*)Ap;
    const uint4* Bsrc = (const uint4*)Bp;

    auto pf = [&](int s, int st) {
        uint32_t da = smem_base + (uint32_t)st * 16384u;
        const uint4* a = Asrc + (size_t)s * 512;
        const uint4* b = Bsrc + (size_t)s * 512;
        #pragma unroll
        for (int i = 0; i < 2; i++) {
            int o = i * 256 + tid;
            cp16(da + (uint32_t)o * 16u, a + o);
            cp16(da + 8192u + (uint32_t)o * 16u, b + o);
        }
    };

    pf(0, 0); CP_COMMIT();
    pf(1, 1); CP_COMMIT();
    pf(2, 2); CP_COMMIT();

    const int NST = HDIM / 32;   // 24 stages
    for (int s = 0; s < NST; s++) {
        CP_WAIT2();
        __syncthreads();
        if (s + 3 < NST) pf(s + 3, (s + 3) & 3);
        CP_COMMIT();
        uint32_t* A = sg + (s & 3) * 4096;
        uint32_t* B = A + 2048;
        #pragma unroll
        for (int kt = 0; kt < 2; kt++) {
            const uint32_t* Ak = A + kt * 1024;
            const uint32_t* Bk = B + kt * 1024;
            uint4 a0 = *(const uint4*)&Ak[((warp_m * 2 + 0) * 32 + lane) * 4];
            uint4 a1 = *(const uint4*)&Ak[((warp_m * 2 + 1) * 32 + lane) * 4];
            #pragma unroll
            for (int ntp = 0; ntp < 4; ntp++) {
                uint4 b = *(const uint4*)&Bk[((warp_n * 4 + ntp) * 32 + lane) * 4];
                mma_f16(acc[0][2 * ntp],     a0.x, a0.y, a0.z, a0.w, b.x, b.y);
                mma_f16(acc[0][2 * ntp + 1], a0.x, a0.y, a0.z, a0.w, b.z, b.w);
                mma_f16(acc[1][2 * ntp],     a1.x, a1.y, a1.z, a1.w, b.x, b.y);
                mma_f16(acc[1][2 * ntp + 1], a1.x, a1.y, a1.z, a1.w, b.z, b.w);
            }
        }
    }
}

#define GEMM_SMEM (4 * 4096 * 4)

// ---------------------------------------------------------------------------
// Projection kernel. Q epilogue pre-scales by CEXP (softmax scale folded in).
// ---------------------------------------------------------------------------
__global__ __launch_bounds__(256)
void proj_kernel(const float* __restrict__ bq, const float* __restrict__ bk,
                 const float* __restrict__ bv) {
    extern __shared__ uint32_t sg[];
    int z = blockIdx.z;
    int mb = blockIdx.y;
    int cnt = g_cnt;
    if (z > 0 && mb * 128 >= cnt) return;

    const uint32_t* Ap = ((z == 0) ? g_xp : g_xkvp) + (size_t)mb * NKT16 * 1024;
    const uint32_t* Bp = g_wp[z] + (size_t)blockIdx.x * NKT16 * 1024;
    const float* bias = (z == 0) ? bq : (z == 1) ? bk : bv;

    float acc[2][8][4] = {};
    gemm_main(sg, Ap, Bp, acc);

    int tid = threadIdx.x;
    int lane = tid & 31, warp = tid >> 5;
    int g = lane >> 2, tg = lane & 3;
    int warp_m = warp & 3, warp_n = warp >> 2;
    int h = blockIdx.x * 2 + warp_n;

    if (z == 0) {
        uint32_t* dst = g_qp + (size_t)(mb * NHEAD + h) * 4096;
        #pragma unroll
        for (int i = 0; i < 2; i++) {
            int mt = warp_m * 2 + i;
            #pragma unroll
            for (int nt = 0; nt < 8; nt++) {
                int dd0 = nt * 8 + 2 * tg;
                float bx = bias[h * 64 + dd0], by = bias[h * 64 + dd0 + 1];
                int kt = nt >> 1;
                uint32_t o = (uint32_t)((kt * 8 + mt) * 32 + lane) * 4 + (nt & 1) * 2;
                uint2 v;
                v.x = pack2((acc[i][nt][0] + bx) * CEXP, (acc[i][nt][1] + by) * CEXP);
                v.y = pack2((acc[i][nt][2] + bx) * CEXP, (acc[i][nt][3] + by) * CEXP);
                *(uint2*)&dst[o] = v;
            }
        }
    } else if (z == 1) {
        #pragma unroll
        for (int i = 0; i < 2; i++) {
            int j0 = mb * 128 + warp_m * 32 + i * 16 + g;
            #pragma unroll
            for (int nt = 0; nt < 8; nt++) {
                int dd0 = nt * 8 + 2 * tg;
                float bx = bias[h * 64 + dd0], by = bias[h * 64 + dd0 + 1];
                int ktp = nt >> 2;
                int wi = ((nt >> 1) & 1) * 2 + (nt & 1);
                #pragma unroll
                for (int r = 0; r < 2; r++) {
                    int j = j0 + r * 8;
                    int T = j >> 6, jj = j & 63;
                    uint32_t base = (uint32_t)(h * 64 + T) * 2048;
                    uint32_t o = base + (uint32_t)(((jj >> 3) * 2 + ktp) * 32
                                 + (jj & 7) * 4 + tg) * 4 + wi;
                    g_k2[o] = pack2(acc[i][nt][r * 2 + 0] + bx,
                                    acc[i][nt][r * 2 + 1] + by);
                }
            }
        }
    } else {
        __half* dst = (__half*)g_v2;
        #pragma unroll
        for (int i = 0; i < 2; i++) {
            int j0 = mb * 128 + warp_m * 32 + i * 16 + g;
            #pragma unroll
            for (int nt = 0; nt < 8; nt++) {
                int dd0 = nt * 8 + 2 * tg;
                float bx = bias[h * 64 + dd0], by = bias[h * 64 + dd0 + 1];
                #pragma unroll
                for (int r = 0; r < 2; r++) {
                    int j = j0 + r * 8;
                    int T = j >> 6, jj = j & 63;
                    int wi = ((jj >> 4) & 1) * 2 + ((jj >> 3) & 1);
                    int ktp = jj >> 5;
                    int lq = (jj >> 1) & 3;
                    int e = jj & 1;
                    #pragma unroll
                    for (int c = 0; c < 2; c++) {
                        int dd = dd0 + c;
                        int l = (dd & 7) * 4 + lq;
                        size_t hidx = (((size_t)(h * 64 + T) * 2048
                                      + ((dd >> 3) * 2 + ktp) * 128 + (l * 4 + wi))) * 2 + e;
                        dst[hidx] = __float2half_rn(acc[i][nt][r * 2 + c] + (c ? by : bx));
                    }
                }
            }
        }
    }
}

__global__ __launch_bounds__(256)
void oproj_kernel(const float* __restrict__ bo, float* __restrict__ out) {
    extern __shared__ uint32_t sg[];
    int mb = blockIdx.y;
    float acc[2][8][4] = {};
    gemm_main(sg, g_ctxp + (size_t)mb * NKT16 * 1024,
              g_wp[3] + (size_t)blockIdx.x * NKT16 * 1024, acc);

    int tid = threadIdx.x;
    int lane = tid & 31, warp = tid >> 5;
    int g = lane >> 2, tg = lane & 3;
    int warp_m = warp & 3, warp_n = warp >> 2;
    int mbase = mb * 128, nbase = blockIdx.x * 128;
    #pragma unroll
    for (int i = 0; i < 2; i++) {
        int m0 = mbase + warp_m * 32 + i * 16 + g;
        #pragma unroll
        for (int nt = 0; nt < 8; nt++) {
            int n0 = nbase + warp_n * 64 + nt * 8 + 2 * tg;
            float bx = bo[n0], by = bo[n0 + 1];
            *(float2*)(out + (size_t)m0 * HDIM + n0) =
                make_float2(acc[i][nt][0] + bx, acc[i][nt][1] + by);
            *(float2*)(out + (size_t)(m0 + 8) * HDIM + n0) =
                make_float2(acc[i][nt][2] + bx, acc[i][nt][3] + by);
        }
    }
}

// ---------------------------------------------------------------------------
// Flash attention: R14 mainloop (double buffer, prefetch-before-wait), Q
// pre-scaled (no scale loop), f16x2 exp, mma denominator. 3 CTAs/SM target.
// ---------------------------------------------------------------------------
#define FLASH_SMEM (8192 * 4)

__global__ __launch_bounds__(128, 3)
void flash_kernel() {
    extern __shared__ uint32_t sm[];
    int tid = threadIdx.x;
    int lane = tid & 31, warp = tid >> 5;
    int tg = lane & 3;
    int h = blockIdx.y, mb = blockIdx.x;
    int cnt = g_cnt;
    uint32_t smem_base = (uint32_t)__cvta_generic_to_shared(sm);

    const uint4* Ksrc = (const uint4*)(g_k2 + (size_t)h * 64 * 2048);
    const uint4* Vsrc = (const uint4*)(g_v2 + (size_t)h * 64 * 2048);
    int ntile = (cnt + 63) >> 6;

    auto prefetch = [&](int t, int buf) {
        uint32_t dk = smem_base + (uint32_t)buf * 16384u;
        const uint4* sk = Ksrc + (size_t)t * 512;
        const uint4* sv = Vsrc + (size_t)t * 512;
        #pragma unroll
        for (int i = 0; i < 4; i++) {
            int o = i * 128 + tid;
            cp16(dk + (uint32_t)o * 16u, sk + o);
            cp16(dk + 8192u + (uint32_t)o * 16u, sv + o);
        }
    };

    prefetch(0, 0);
    CP_COMMIT();

    // Q fragments (pre-scaled by CEXP at projection)
    const uint32_t* Qsrc = g_qp + (size_t)(mb * NHEAD + h) * 4096;
    uint4 q[4][2];
    #pragma unroll
    for (int kt = 0; kt < 4; kt++)
        #pragma unroll
        for (int mtl = 0; mtl < 2; mtl++)
            q[kt][mtl] = *(const uint4*)&Qsrc[((kt * 8 + warp * 2 + mtl) * 32 + lane) * 4];

    float lacc[2][4] = {};
    float acc[2][8][4] = {};

    for (int t = 0; t < ntile; t++) {
        int cur = t & 1;
        int kvb = t * 64;
        __syncthreads();
        if (t + 1 < ntile) prefetch(t + 1, cur ^ 1);
        CP_COMMIT();
        CP_WAIT1();
        __syncthreads();
        uint32_t* Kp = sm + cur * 4096;
        uint32_t* Vp = Kp + 2048;

        // S = Q K^T (warp: 32x64), pre-scaled
        float sc[2][8][4] = {};
        #pragma unroll
        for (int ktp = 0; ktp < 2; ktp++) {
            #pragma unroll
            for (int nt = 0; nt < 8; nt++) {
                uint4 kb = *(const uint4*)&Kp[((nt * 2 + ktp) * 32 + lane) * 4];
                #pragma unroll
                for (int mtl = 0; mtl < 2; mtl++) {
                    uint4 a = q[2 * ktp][mtl];
                    mma_f16(sc[mtl][nt], a.x, a.y, a.z, a.w, kb.x, kb.y);
                    uint4 a2 = q[2 * ktp + 1][mtl];
                    mma_f16(sc[mtl][nt], a2.x, a2.y, a2.z, a2.w, kb.z, kb.w);
                }
            }
        }

        bool tail = (kvb + 64 > cnt);
        uint32_t pA[4][2][4];
        #pragma unroll
        for (int mtl = 0; mtl < 2; mtl++) {
            if (tail) {
                #pragma unroll
                for (int nt = 0; nt < 8; nt++) {
                    int c0 = kvb + nt * 8 + 2 * tg;
                    if (c0     >= cnt) { sc[mtl][nt][0] = -1e30f; sc[mtl][nt][2] = -1e30f; }
                    if (c0 + 1 >= cnt) { sc[mtl][nt][1] = -1e30f; sc[mtl][nt][3] = -1e30f; }
                }
            }
            // pack to half2, exp2 in f16x2 -> P fragments directly
            #pragma unroll
            for (int kt = 0; kt < 4; kt++) {
                pA[kt][mtl][0] = h2ex2(pack2(sc[mtl][2 * kt][0],     sc[mtl][2 * kt][1]));
                pA[kt][mtl][1] = h2ex2(pack2(sc[mtl][2 * kt][2],     sc[mtl][2 * kt][3]));
                pA[kt][mtl][2] = h2ex2(pack2(sc[mtl][2 * kt + 1][0], sc[mtl][2 * kt + 1][1]));
                pA[kt][mtl][3] = h2ex2(pack2(sc[mtl][2 * kt + 1][2], sc[mtl][2 * kt + 1][3]));
            }
            // denominator: lacc += P @ ones
            #pragma unroll
            for (int kt = 0; kt < 4; kt++)
                mma_f16(lacc[mtl], pA[kt][mtl][0], pA[kt][mtl][1],
                        pA[kt][mtl][2], pA[kt][mtl][3], ONES_H2, ONES_H2);
        }

        // acc += P @ V
        #pragma unroll
        for (int ktp = 0; ktp < 2; ktp++) {
            #pragma unroll
            for (int nt = 0; nt < 8; nt++) {
                uint4 vb = *(const uint4*)&Vp[((nt * 2 + ktp) * 32 + lane) * 4];
                #pragma unroll
                for (int mtl = 0; mtl < 2; mtl++) {
                    uint32_t* a = pA[2 * ktp][mtl];
                    mma_f16(acc[mtl][nt], a[0], a[1], a[2], a[3], vb.x, vb.y);
                    uint32_t* a2 = pA[2 * ktp + 1][mtl];
                    mma_f16(acc[mtl][nt], a2[0], a2[1], a2[2], a2[3], vb.z, vb.w);
                }
            }
        }
    }

    // epilogue: lacc[mtl][0] = row-g sum, lacc[mtl][2] = row-(g+8) sum
    #pragma unroll
    for (int mtl = 0; mtl < 2; mtl++) {
        float i0 = 1.0f / lacc[mtl][0], i1 = 1.0f / lacc[mtl][2];
        int mt = warp * 2 + mtl;
        #pragma unroll
        for (int nt = 0; nt < 8; nt++) {
            int kt16 = h * 4 + (nt >> 1);
            uint32_t o = ((uint32_t)(mb * NKT16 + kt16) * 8 + mt) * 128
                       + lane * 4 + (nt & 1) * 2;
            uint2 v;
            v.x = pack2(acc[mtl][nt][0] * i0, acc[mtl][nt][1] * i0);
            v.y = pack2(acc[mtl][nt][2] * i1, acc[mtl][nt][3] * i1);
            *(uint2*)&g_ctxp[o] = v;
        }
    }
}

// ---------------------------------------------------------------------------
extern "C" void kernel_launch(void* const* d_in, const int* in_sizes, int n_in,
                              void* d_out, int out_size) {
    const float* x  = (const float*)d_in[0];
    const float* Wq = (const float*)d_in[1];
    const float* bq = (const float*)d_in[2];
    const float* Wk = (const float*)d_in[3];
    const float* bk = (const float*)d_in[4];
    const float* Wv = (const float*)d_in[5];
    const float* bv = (const float*)d_in[6];
    const float* Wo = (const float*)d_in[7];
    const float* bo = (const float*)d_in[8];
    const int*   mask = (const int*)d_in[9];
    float* out = (float*)d_out;

    cudaFuncSetAttribute(flash_kernel, cudaFuncAttributeMaxDynamicSharedMemorySize,
                         FLASH_SMEM);
    cudaFuncSetAttribute(proj_kernel, cudaFuncAttributeMaxDynamicSharedMemorySize,
                         GEMM_SMEM);
    cudaFuncSetAttribute(oproj_kernel, cudaFuncAttributeMaxDynamicSharedMemorySize,
                         GEMM_SMEM);

    compact_kernel<<<1, 1024>>>(mask);
    permute_x_kernel<<<dim3(NKT16, 32, 2), 256>>>(x);
    permute_w_kernel<<<dim3(NKT16, 6, 4), 256>>>(Wq, Wk, Wv, Wo);
    proj_kernel<<<dim3(6, 32, 3), 256, GEMM_SMEM>>>(bq, bk, bv);
    flash_kernel<<<dim3(SEQ / 128, NHEAD), 128, FLASH_SMEM>>>();
    oproj_kernel<<<dim3(6, 32), 256, GEMM_SMEM>>>(bo, out);
}